// round 2
// baseline (speedup 1.0000x reference)
#include <cuda_runtime.h>

#define NB   32
#define TT   1024
#define CC_  512
#define KK   64
#define F_EPS 1e-12f

// Scratch (allocation-free rule: __device__ globals)
__device__ float g_a[(size_t)NB * TT * KK];      // [n][t][k]  8 MB
__device__ float g_vlad[(size_t)NB * KK * CC_];  // [n][k][c]  4 MB

// ---------------------------------------------------------------------------
// Kernel A: logits GEMM + softmax over K.
// grid (8, 32): blockIdx.x = t-tile of 128, blockIdx.y = n. 256 threads.
// Thread (tg = tid%32, kg = tid/32) computes t = tg+32i (i<4), k = kg*8+j (j<8).
// smem: xs[32][129] (c-major, t contig), ws[32][65] (c-major, k contig);
// reused as ls[128][65] for the softmax. All accesses bank-conflict-free.
// ---------------------------------------------------------------------------
__global__ __launch_bounds__(256) void assign_kernel(
    const float* __restrict__ x, const float* __restrict__ W,
    const float* __restrict__ b)
{
    __shared__ float smem[128 * 65];     // 8320 floats = 33.3 KB (max of phases)
    float* xs = smem;                    // 32*129 = 4128
    float* ws = smem + 32 * 129;         // 32*65  = 2080  (total 6208 <= 8320)

    const int n  = blockIdx.y;
    const int t0 = blockIdx.x * 128;
    const int tid = threadIdx.x;
    const int tg = tid & 31;
    const int kg = tid >> 5;

    float acc[4][8];
#pragma unroll
    for (int i = 0; i < 4; i++)
#pragma unroll
        for (int j = 0; j < 8; j++) acc[i][j] = 0.f;

    const float* xbase = x + ((size_t)n * TT + t0) * CC_;

    for (int c0 = 0; c0 < CC_; c0 += 32) {
        // load x tile transposed: xs[c][t], 4096 floats
#pragma unroll
        for (int r = 0; r < 4; r++) {
            int idx = tid + 256 * r;          // 0..1023 float4s
            int t   = idx >> 3;               // 8 float4 per 32-c row
            int c4  = (idx & 7) * 4;
            float4 v = *reinterpret_cast<const float4*>(xbase + (size_t)t * CC_ + c0 + c4);
            xs[(c4 + 0) * 129 + t] = v.x;
            xs[(c4 + 1) * 129 + t] = v.y;
            xs[(c4 + 2) * 129 + t] = v.z;
            xs[(c4 + 3) * 129 + t] = v.w;
        }
        // load W tile transposed: ws[c][k], 2048 floats
#pragma unroll
        for (int r = 0; r < 2; r++) {
            int idx = tid + 256 * r;          // 0..511 float4s
            int k   = idx >> 3;
            int c4  = (idx & 7) * 4;
            float4 v = *reinterpret_cast<const float4*>(W + (size_t)k * CC_ + c0 + c4);
            ws[(c4 + 0) * 65 + k] = v.x;
            ws[(c4 + 1) * 65 + k] = v.y;
            ws[(c4 + 2) * 65 + k] = v.z;
            ws[(c4 + 3) * 65 + k] = v.w;
        }
        __syncthreads();
#pragma unroll
        for (int cc = 0; cc < 32; cc++) {
            float xv[4], wv[8];
#pragma unroll
            for (int i = 0; i < 4; i++) xv[i] = xs[cc * 129 + tg + 32 * i];
#pragma unroll
            for (int j = 0; j < 8; j++) wv[j] = ws[cc * 65 + kg * 8 + j];
#pragma unroll
            for (int i = 0; i < 4; i++)
#pragma unroll
                for (int j = 0; j < 8; j++) acc[i][j] += xv[i] * wv[j];
        }
        __syncthreads();
    }

    // write logits (+bias) to smem as ls[128][65]
    float* ls = smem;
    float bb[8];
#pragma unroll
    for (int j = 0; j < 8; j++) bb[j] = b[kg * 8 + j];
#pragma unroll
    for (int i = 0; i < 4; i++)
#pragma unroll
        for (int j = 0; j < 8; j++)
            ls[(tg + 32 * i) * 65 + kg * 8 + j] = acc[i][j] + bb[j];
    __syncthreads();

    // softmax over k for each of 128 rows; threads 0..127 take one row each
    if (tid < 128) {
        const int t = tid;
        float m = -1e30f;
#pragma unroll
        for (int k = 0; k < KK; k++) m = fmaxf(m, ls[t * 65 + k]);
        float s = 0.f;
#pragma unroll
        for (int k = 0; k < KK; k++) s += __expf(ls[t * 65 + k] - m);
        const float inv = 1.f / s;
        float* aout = g_a + ((size_t)n * TT + t0 + t) * KK;
#pragma unroll
        for (int k4 = 0; k4 < KK; k4 += 4) {
            float4 v;
            v.x = __expf(ls[t * 65 + k4 + 0] - m) * inv;
            v.y = __expf(ls[t * 65 + k4 + 1] - m) * inv;
            v.z = __expf(ls[t * 65 + k4 + 2] - m) * inv;
            v.w = __expf(ls[t * 65 + k4 + 3] - m) * inv;
            *reinterpret_cast<float4*>(aout + k4) = v;
        }
    }
}

// ---------------------------------------------------------------------------
// Kernel B: vlad[n,k,c] = sum_t a[n,t,k]*x[n,t,c] - asum[n,k]*centroid[k,c]
// grid (4, 32): blockIdx.x = c-tile of 128, blockIdx.y = n. 256 threads.
// Thread (cg = tid%32, kg = tid/32): c = cg+32i (i<4), k = kg*8+j (j<8).
// smem: as[64][64] (t-major, k contig), xsm[64][128] (t-major, c contig).
// ---------------------------------------------------------------------------
__global__ __launch_bounds__(256) void vlad_kernel(
    const float* __restrict__ x, const float* __restrict__ centroids)
{
    __shared__ float as_[64 * 64];    // 16 KB
    __shared__ float xsm[64 * 128];   // 32 KB

    const int n  = blockIdx.y;
    const int c0 = blockIdx.x * 128;
    const int tid = threadIdx.x;
    const int cg = tid & 31;
    const int kg = tid >> 5;

    float acc[8][4];
#pragma unroll
    for (int j = 0; j < 8; j++)
#pragma unroll
        for (int i = 0; i < 4; i++) acc[j][i] = 0.f;
    float asum_loc = 0.f;

    const float* abase = g_a + (size_t)n * TT * KK;
    const float* xbase = x + (size_t)n * TT * CC_ + c0;

    for (int t0 = 0; t0 < TT; t0 += 64) {
        // a chunk: 64 t x 64 k contiguous -> linear copy (4096 floats)
#pragma unroll
        for (int r = 0; r < 4; r++) {
            int idx4 = (tid + 256 * r) * 4;
            *reinterpret_cast<float4*>(as_ + idx4) =
                *reinterpret_cast<const float4*>(abase + (size_t)t0 * KK + idx4);
        }
        // x chunk: 64 t x 128 c (8192 floats)
#pragma unroll
        for (int r = 0; r < 8; r++) {
            int idx = tid + 256 * r;          // 0..2047 float4s
            int t   = idx >> 5;               // 32 float4 per 128-c row
            int c4  = (idx & 31) * 4;
            *reinterpret_cast<float4*>(xsm + t * 128 + c4) =
                *reinterpret_cast<const float4*>(xbase + (size_t)(t0 + t) * CC_ + c4);
        }
        __syncthreads();

        if (tid < KK) {
#pragma unroll
            for (int t = 0; t < 64; t++) asum_loc += as_[t * KK + tid];
        }
#pragma unroll 4
        for (int t = 0; t < 64; t++) {
            float wv[8], xv[4];
#pragma unroll
            for (int j = 0; j < 8; j++) wv[j] = as_[t * KK + kg * 8 + j];
#pragma unroll
            for (int i = 0; i < 4; i++) xv[i] = xsm[t * 128 + cg + 32 * i];
#pragma unroll
            for (int j = 0; j < 8; j++)
#pragma unroll
                for (int i = 0; i < 4; i++) acc[j][i] += wv[j] * xv[i];
        }
        __syncthreads();
    }

    // broadcast asum via smem (reuse as_)
    if (tid < KK) as_[tid] = asum_loc;
    __syncthreads();

    float* vout = g_vlad + (size_t)n * KK * CC_ + c0;
    const float* cent = centroids + c0;
#pragma unroll
    for (int j = 0; j < 8; j++) {
        const int k = kg * 8 + j;
        const float asum = as_[k];
#pragma unroll
        for (int i = 0; i < 4; i++) {
            const int c = cg + 32 * i;
            vout[(size_t)k * CC_ + c] = acc[j][i] - asum * cent[(size_t)k * CC_ + c];
        }
    }
}

// ---------------------------------------------------------------------------
// Kernel C: intra-normalize per (n,k) over C, then global L2 per n.
// grid 32 (one CTA per n), 256 threads (8 warps).
// ---------------------------------------------------------------------------
__global__ __launch_bounds__(256) void norm_kernel(float* __restrict__ out)
{
    const int n = blockIdx.x;
    const int tid = threadIdx.x;
    const int warp = tid >> 5, lane = tid & 31;
    __shared__ float sscale[KK];
    __shared__ float sred[8];

    const float* v = g_vlad + (size_t)n * KK * CC_;

    // per-row sum of squares (8 rows per warp)
    for (int k = warp; k < KK; k += 8) {
        float ss = 0.f;
        const float* row = v + (size_t)k * CC_;
        for (int c = lane * 4; c < CC_; c += 128) {
            float4 q = *reinterpret_cast<const float4*>(row + c);
            ss += q.x * q.x + q.y * q.y + q.z * q.z + q.w * q.w;
        }
#pragma unroll
        for (int off = 16; off; off >>= 1) ss += __shfl_xor_sync(0xffffffffu, ss, off);
        if (lane == 0) sscale[k] = ss;
    }
    __syncthreads();

    // per-row scale + global sumsq of normalized rows
    float gpart = 0.f;
    if (tid < KK) {
        float ss = sscale[tid];
        float sc = 1.f / fmaxf(sqrtf(ss), F_EPS);
        gpart = ss * sc * sc;
        sscale[tid] = sc;
    }
#pragma unroll
    for (int off = 16; off; off >>= 1) gpart += __shfl_xor_sync(0xffffffffu, gpart, off);
    if (lane == 0) sred[warp] = gpart;
    __syncthreads();
    if (tid == 0) sred[0] = 1.f / fmaxf(sqrtf(sred[0] + sred[1]), F_EPS);
    __syncthreads();
    const float gscale = sred[0];

    float* o = out + (size_t)n * KK * CC_;
    for (int idx = tid * 4; idx < KK * CC_; idx += 1024) {
        const int k = idx >> 9;                 // idx/512, whole float4 in one row
        const float s = sscale[k] * gscale;
        float4 q = *reinterpret_cast<const float4*>(v + idx);
        q.x *= s; q.y *= s; q.z *= s; q.w *= s;
        *reinterpret_cast<float4*>(o + idx) = q;
    }
}

// ---------------------------------------------------------------------------
extern "C" void kernel_launch(void* const* d_in, const int* in_sizes, int n_in,
                              void* d_out, int out_size)
{
    const float* x    = (const float*)d_in[0];   // [32,1024,512]
    const float* W    = (const float*)d_in[1];   // [64,512]
    const float* b    = (const float*)d_in[2];   // [64]
    const float* cent = (const float*)d_in[3];   // [64,512]
    float* out = (float*)d_out;                  // [32, 32768]

    assign_kernel<<<dim3(8, 32), 256>>>(x, W, b);
    vlad_kernel<<<dim3(4, 32), 256>>>(x, cent);
    norm_kernel<<<32, 256>>>(out);
}

// round 5
// speedup vs baseline: 1.8123x; 1.8123x over previous
#include <cuda_runtime.h>
#include <cuda_bf16.h>
#include <stdint.h>

#define NB   32
#define TT   1024
#define CC_  512
#define KK   64
#define F_EPS 1e-12f

// ---------------------------------------------------------------------------
// Scratch (__device__ globals; allocation-free rule)
// ---------------------------------------------------------------------------
__device__ __nv_bfloat16 g_ahi[(size_t)NB * KK * TT];    // a hi split, [n][k][t]
__device__ __nv_bfloat16 g_alo[(size_t)NB * KK * TT];    // a lo split, [n][k][t]
__device__ float         g_asum_part[NB * 8 * KK];       // per t-tile partial sums
__device__ float         g_vlad[(size_t)NB * KK * CC_];  // [n][k][c]

// ---------------------------------------------------------------------------
// Helpers (plain sm_80+ PTX only: ldmatrix + mma.sync, no 'a' features)
// ---------------------------------------------------------------------------
__device__ __forceinline__ uint32_t smem_u32(const void* p) {
    uint32_t a;
    asm("{ .reg .u64 t; cvta.to.shared.u64 t, %1; cvt.u32.u64 %0, t; }"
        : "=r"(a) : "l"(p));
    return a;
}

__device__ __forceinline__ uint32_t swz128(uint32_t off) {  // Swizzle<3,4,3>
    return off ^ ((off >> 3) & 0x70);
}

__device__ __forceinline__ void ldmx4(uint32_t* r, uint32_t addr) {
    asm volatile("ldmatrix.sync.aligned.m8n8.x4.shared.b16 {%0,%1,%2,%3}, [%4];"
                 : "=r"(r[0]), "=r"(r[1]), "=r"(r[2]), "=r"(r[3]) : "r"(addr));
}

__device__ __forceinline__ void mma_bf16(float* d, const uint32_t* a, const uint32_t* b) {
    asm volatile("mma.sync.aligned.m16n8k16.row.col.f32.bf16.bf16.f32 "
                 "{%0,%1,%2,%3}, {%4,%5,%6,%7}, {%8,%9}, {%0,%1,%2,%3};"
                 : "+f"(d[0]), "+f"(d[1]), "+f"(d[2]), "+f"(d[3])
                 : "r"(a[0]), "r"(a[1]), "r"(a[2]), "r"(a[3]), "r"(b[0]), "r"(b[1]));
}

__device__ __forceinline__ uint32_t pack_bf16x2(float lo, float hi) {
    __nv_bfloat162 v = __floats2bfloat162_rn(lo, hi);
    return reinterpret_cast<uint32_t&>(v);
}

__device__ __forceinline__ void split2(float v, float& h, float& l) {
    __nv_bfloat16 hb = __float2bfloat16(v);
    h = __bfloat162float(hb);
    l = v - h;
}

// smem layout (byte offsets from 1024-aligned base)
#define OA_HI   0u        // A: 128 rows x 128B (SW128)          16 KB
#define OA_LO   16384u
#define OB_HI   32768u    // B: 64 rows x 128B (SW128)            8 KB
#define OB_LO   40960u
#define OAUX    49152u    // 64 floats (bias / asum)
#define OSROW   49408u    // 128 floats (softmax 1/sum)
#define SMEM_SZ (49920u + 1024u)
#define LSTR    66        // fp32 epilogue tile stride

// ---------------------------------------------------------------------------
// Shared warp-level MMA over one 64-deep chunk.
// A tile: 128 rows (m) x 64 bf16 (SW128); B tile: 64 rows (n) x 64 bf16.
// Warp computes acc[2][4][4] covering 32 m x 32 n. Three passes: hh, hl, lh.
// ---------------------------------------------------------------------------
__device__ __forceinline__ void warp_mma_chunk(
    float (&acc)[2][4][4],
    uint32_t aHi, uint32_t aLo, uint32_t bHi, uint32_t bLo,
    int mBase, int nBase, int lane)
{
    const int arow  = mBase + (lane & 15);
    const int acol0 = (lane >> 4) * 16;                       // bytes within row
    const int brow  = nBase + ((lane >> 4) << 3) + (lane & 7);
    const int bcol0 = ((lane >> 3) & 1) * 16;
#pragma unroll
    for (int ks = 0; ks < 4; ks++) {
        uint32_t ah[2][4], al[2][4], bh[2][4], bl[2][4];
#pragma unroll
        for (int mb = 0; mb < 2; mb++) {
            uint32_t off = swz128((uint32_t)((arow + mb * 16) * 128 + ks * 32 + acol0));
            ldmx4(ah[mb], aHi + off);
            ldmx4(al[mb], aLo + off);
        }
#pragma unroll
        for (int np = 0; np < 2; np++) {
            uint32_t off = swz128((uint32_t)((brow + np * 16) * 128 + ks * 32 + bcol0));
            ldmx4(bh[np], bHi + off);
            ldmx4(bl[np], bLo + off);
        }
#pragma unroll
        for (int mb = 0; mb < 2; mb++)
#pragma unroll
            for (int nb = 0; nb < 4; nb++) {
                const uint32_t* ph = &bh[nb >> 1][(nb & 1) * 2];
                const uint32_t* pl = &bl[nb >> 1][(nb & 1) * 2];
                mma_bf16(acc[mb][nb], ah[mb], ph);
                mma_bf16(acc[mb][nb], ah[mb], pl);
                mma_bf16(acc[mb][nb], al[mb], ph);
            }
    }
}

// Store warp accumulators into fp32 smem tile ls[row][col], stride LSTR.
__device__ __forceinline__ void store_frags(
    float* ls, float (&acc)[2][4][4], int mBase, int nBase, int lane)
{
    const int r = lane >> 2, cp = (lane & 3) * 2;
#pragma unroll
    for (int mb = 0; mb < 2; mb++)
#pragma unroll
        for (int nb = 0; nb < 4; nb++) {
            const int row = mBase + mb * 16 + r;
            const int col = nBase + nb * 8 + cp;
            ls[row * LSTR + col]           = acc[mb][nb][0];
            ls[row * LSTR + col + 1]       = acc[mb][nb][1];
            ls[(row + 8) * LSTR + col]     = acc[mb][nb][2];
            ls[(row + 8) * LSTR + col + 1] = acc[mb][nb][3];
        }
}

// ---------------------------------------------------------------------------
// Kernel 1: logits GEMM + softmax over K + bf16 split writeback + asum partials
// grid (8, 32): x = t-tile of 128, y = n. 256 threads (8 warps, 4m x 2n).
// ---------------------------------------------------------------------------
__global__ __launch_bounds__(256, 2)
void assign_mma_kernel(const float* __restrict__ x, const float* __restrict__ W,
                       const float* __restrict__ b)
{
    extern __shared__ char smem_raw[];
    uint32_t sb0 = smem_u32(smem_raw);
    uint32_t abase = (sb0 + 1023u) & ~1023u;
    char* sm = smem_raw + (abase - sb0);

    const int n   = blockIdx.y;
    const int t0  = blockIdx.x * 128;
    const int tid = threadIdx.x;
    const int wid = tid >> 5, lane = tid & 31;
    const int mBase = (wid & 3) * 32, nBase = (wid >> 2) * 32;

    float* saux = (float*)(sm + OAUX);
    float* srow = (float*)(sm + OSROW);
    if (tid < KK) saux[tid] = b[tid];

    float acc[2][4][4];
#pragma unroll
    for (int mb = 0; mb < 2; mb++)
#pragma unroll
        for (int nb = 0; nb < 4; nb++)
#pragma unroll
            for (int e = 0; e < 4; e++) acc[mb][nb][e] = 0.f;

    const float* xb = x + ((size_t)(n * TT + t0)) * CC_;

    for (int ci = 0; ci < 8; ci++) {
        const int c0 = ci * 64;
        // A: x tile [128 t x 64 c] fp32 -> hi/lo bf16 (2048 float4 tasks)
#pragma unroll
        for (int r = 0; r < 8; r++) {
            int idx = tid + 256 * r;
            int t = idx >> 4, c4 = (idx & 15) * 4;
            float4 v = *reinterpret_cast<const float4*>(xb + (size_t)t * CC_ + c0 + c4);
            float h0,h1,h2,h3,l0,l1,l2,l3;
            split2(v.x,h0,l0); split2(v.y,h1,l1); split2(v.z,h2,l2); split2(v.w,h3,l3);
            uint2 uh = { pack_bf16x2(h0,h1), pack_bf16x2(h2,h3) };
            uint2 ul = { pack_bf16x2(l0,l1), pack_bf16x2(l2,l3) };
            uint32_t sw = swz128((uint32_t)(t * 128 + c4 * 2));
            *reinterpret_cast<uint2*>(sm + OA_HI + sw) = uh;
            *reinterpret_cast<uint2*>(sm + OA_LO + sw) = ul;
        }
        // B: W tile [64 k x 64 c] (1024 float4 tasks)
#pragma unroll
        for (int r = 0; r < 4; r++) {
            int idx = tid + 256 * r;
            int k = idx >> 4, c4 = (idx & 15) * 4;
            float4 v = *reinterpret_cast<const float4*>(W + (size_t)k * CC_ + c0 + c4);
            float h0,h1,h2,h3,l0,l1,l2,l3;
            split2(v.x,h0,l0); split2(v.y,h1,l1); split2(v.z,h2,l2); split2(v.w,h3,l3);
            uint2 uh = { pack_bf16x2(h0,h1), pack_bf16x2(h2,h3) };
            uint2 ul = { pack_bf16x2(l0,l1), pack_bf16x2(l2,l3) };
            uint32_t sw = swz128((uint32_t)(k * 128 + c4 * 2));
            *reinterpret_cast<uint2*>(sm + OB_HI + sw) = uh;
            *reinterpret_cast<uint2*>(sm + OB_LO + sw) = ul;
        }
        __syncthreads();
        warp_mma_chunk(acc, abase + OA_HI, abase + OA_LO, abase + OB_HI, abase + OB_LO,
                       mBase, nBase, lane);
        __syncthreads();
    }

    // Epilogue: logits -> smem ls[t][k], softmax per row, bf16 split writeback.
    float* ls = (float*)sm;
    store_frags(ls, acc, mBase, nBase, lane);
    __syncthreads();

    if (tid < 128) {
        const int t = tid;
        float mx = -1e30f;
#pragma unroll 8
        for (int k = 0; k < KK; k++) mx = fmaxf(mx, ls[t * LSTR + k] + saux[k]);
        float s = 0.f;
#pragma unroll 8
        for (int k = 0; k < KK; k++) {
            float e = __expf(ls[t * LSTR + k] + saux[k] - mx);
            ls[t * LSTR + k] = e;
            s += e;
        }
        srow[t] = 1.f / s;
    }
    __syncthreads();

    // Output: pack 4 t per 8B store; deterministic asum partials per block.
#pragma unroll
    for (int i = 0; i < 8; i++) {
        int idx = tid + 256 * i;
        int k = idx >> 5;                 // = wid + 8*i (uniform per warp)
        int tq = (idx & 31) * 4;          // = lane*4
        float a0 = ls[(tq + 0) * LSTR + k] * srow[tq + 0];
        float a1 = ls[(tq + 1) * LSTR + k] * srow[tq + 1];
        float a2 = ls[(tq + 2) * LSTR + k] * srow[tq + 2];
        float a3 = ls[(tq + 3) * LSTR + k] * srow[tq + 3];
        float h0,h1,h2,h3,l0,l1,l2,l3;
        split2(a0,h0,l0); split2(a1,h1,l1); split2(a2,h2,l2); split2(a3,h3,l3);
        uint2 uh = { pack_bf16x2(h0,h1), pack_bf16x2(h2,h3) };
        uint2 ul = { pack_bf16x2(l0,l1), pack_bf16x2(l2,l3) };
        size_t off = ((size_t)(n * KK + k)) * TT + t0 + tq;
        *reinterpret_cast<uint2*>(g_ahi + off) = uh;
        *reinterpret_cast<uint2*>(g_alo + off) = ul;

        float p = a0 + a1 + a2 + a3;
#pragma unroll
        for (int o = 16; o; o >>= 1) p += __shfl_xor_sync(0xffffffffu, p, o);
        if (lane == 0) g_asum_part[(n * 8 + blockIdx.x) * KK + k] = p;
    }
}

// ---------------------------------------------------------------------------
// Kernel 2: vlad GEMM. grid (4, 32): x = c-tile of 128, y = n. 256 threads.
// D[c,k] = sum_t xT[c,t]*a[k,t]; epilogue subtracts asum[k]*centroid[k,c].
// ---------------------------------------------------------------------------
__global__ __launch_bounds__(256, 2)
void vlad_mma_kernel(const float* __restrict__ x, const float* __restrict__ cent)
{
    extern __shared__ char smem_raw[];
    uint32_t sb0 = smem_u32(smem_raw);
    uint32_t abase = (sb0 + 1023u) & ~1023u;
    char* sm = smem_raw + (abase - sb0);

    const int n   = blockIdx.y;
    const int c0  = blockIdx.x * 128;
    const int tid = threadIdx.x;
    const int wid = tid >> 5, lane = tid & 31;
    const int mBase = (wid & 3) * 32, nBase = (wid >> 2) * 32;

    float* saux = (float*)(sm + OAUX);
    if (tid < KK) {
        float s = 0.f;
#pragma unroll
        for (int p = 0; p < 8; p++) s += g_asum_part[(n * 8 + p) * KK + tid];
        saux[tid] = s;
    }

    float acc[2][4][4];
#pragma unroll
    for (int mb = 0; mb < 2; mb++)
#pragma unroll
        for (int nb = 0; nb < 4; nb++)
#pragma unroll
            for (int e = 0; e < 4; e++) acc[mb][nb][e] = 0.f;

    for (int ti = 0; ti < 16; ti++) {
        const int tch = ti * 64;
        // A: x chunk [64 t x 128 c] fp32, transposed store -> [128 c x 64 t] bf16
        const float* xb = x + ((size_t)(n * TT + tch)) * CC_ + c0;
#pragma unroll
        for (int r = 0; r < 8; r++) {
            int idx = tid + 256 * r;                 // 2048 tasks: (c, t-quad)
            int c = idx & 127, t = (idx >> 7) * 4;
            float v0 = xb[(size_t)(t + 0) * CC_ + c];
            float v1 = xb[(size_t)(t + 1) * CC_ + c];
            float v2 = xb[(size_t)(t + 2) * CC_ + c];
            float v3 = xb[(size_t)(t + 3) * CC_ + c];
            float h0,h1,h2,h3,l0,l1,l2,l3;
            split2(v0,h0,l0); split2(v1,h1,l1); split2(v2,h2,l2); split2(v3,h3,l3);
            uint2 uh = { pack_bf16x2(h0,h1), pack_bf16x2(h2,h3) };
            uint2 ul = { pack_bf16x2(l0,l1), pack_bf16x2(l2,l3) };
            uint32_t sw = swz128((uint32_t)(c * 128 + t * 2));
            *reinterpret_cast<uint2*>(sm + OA_HI + sw) = uh;
            *reinterpret_cast<uint2*>(sm + OA_LO + sw) = ul;
        }
        // B: a chunk [64 k x 64 t] bf16, straight swizzled copy (512 x 16B)
#pragma unroll
        for (int r = 0; r < 2; r++) {
            int idx = tid + 256 * r;
            int k = idx >> 3, e8 = (idx & 7) * 8;    // 8 bf16 per 16B
            size_t goff = ((size_t)(n * KK + k)) * TT + tch + e8;
            uint32_t sw = swz128((uint32_t)(k * 128 + e8 * 2));
            *reinterpret_cast<uint4*>(sm + OB_HI + sw) =
                *reinterpret_cast<const uint4*>(g_ahi + goff);
            *reinterpret_cast<uint4*>(sm + OB_LO + sw) =
                *reinterpret_cast<const uint4*>(g_alo + goff);
        }
        __syncthreads();
        warp_mma_chunk(acc, abase + OA_HI, abase + OA_LO, abase + OB_HI, abase + OB_LO,
                       mBase, nBase, lane);
        __syncthreads();
    }

    // Epilogue: D[c][k] -> smem, then transposed coalesced writeback minus asum*cent
    float* vs = (float*)sm;
    store_frags(vs, acc, mBase, nBase, lane);
    __syncthreads();

#pragma unroll
    for (int i = 0; i < 8; i++) {
        int idx = tid + 256 * i;
        int k = idx >> 5;
        int cq = (idx & 31) * 4;
        const float as = saux[k];
        const float* cp = cent + (size_t)k * CC_ + c0 + cq;
        float4 cv = *reinterpret_cast<const float4*>(cp);
        float4 o;
        o.x = vs[(cq + 0) * LSTR + k] - as * cv.x;
        o.y = vs[(cq + 1) * LSTR + k] - as * cv.y;
        o.z = vs[(cq + 2) * LSTR + k] - as * cv.z;
        o.w = vs[(cq + 3) * LSTR + k] - as * cv.w;
        *reinterpret_cast<float4*>(g_vlad + ((size_t)(n * KK + k)) * CC_ + c0 + cq) = o;
    }
}

// ---------------------------------------------------------------------------
// Kernel 3: intra-normalize per (n,k) over C, then global L2 per n.
// ---------------------------------------------------------------------------
__global__ __launch_bounds__(256) void norm_kernel(float* __restrict__ out)
{
    const int n = blockIdx.x;
    const int tid = threadIdx.x;
    const int warp = tid >> 5, lane = tid & 31;
    __shared__ float sscale[KK];
    __shared__ float sred[8];

    const float* v = g_vlad + (size_t)n * KK * CC_;

    for (int k = warp; k < KK; k += 8) {
        float ss = 0.f;
        const float* row = v + (size_t)k * CC_;
        for (int c = lane * 4; c < CC_; c += 128) {
            float4 q = *reinterpret_cast<const float4*>(row + c);
            ss += q.x * q.x + q.y * q.y + q.z * q.z + q.w * q.w;
        }
#pragma unroll
        for (int off = 16; off; off >>= 1) ss += __shfl_xor_sync(0xffffffffu, ss, off);
        if (lane == 0) sscale[k] = ss;
    }
    __syncthreads();

    float gpart = 0.f;
    if (tid < KK) {
        float ss = sscale[tid];
        float sc = 1.f / fmaxf(sqrtf(ss), F_EPS);
        gpart = ss * sc * sc;
        sscale[tid] = sc;
    }
#pragma unroll
    for (int off = 16; off; off >>= 1) gpart += __shfl_xor_sync(0xffffffffu, gpart, off);
    if (lane == 0) sred[warp] = gpart;
    __syncthreads();
    if (tid == 0) sred[0] = 1.f / fmaxf(sqrtf(sred[0] + sred[1]), F_EPS);
    __syncthreads();
    const float gscale = sred[0];

    float* o = out + (size_t)n * KK * CC_;
    for (int idx = tid * 4; idx < KK * CC_; idx += 1024) {
        const int k = idx >> 9;
        const float s = sscale[k] * gscale;
        float4 q = *reinterpret_cast<const float4*>(v + idx);
        q.x *= s; q.y *= s; q.z *= s; q.w *= s;
        *reinterpret_cast<float4*>(o + idx) = q;
    }
}

// ---------------------------------------------------------------------------
extern "C" void kernel_launch(void* const* d_in, const int* in_sizes, int n_in,
                              void* d_out, int out_size)
{
    const float* x    = (const float*)d_in[0];   // [32,1024,512]
    const float* W    = (const float*)d_in[1];   // [64,512]
    const float* b    = (const float*)d_in[2];   // [64]
    const float* cent = (const float*)d_in[3];   // [64,512]
    float* out = (float*)d_out;                  // [32, 32768]

    cudaFuncSetAttribute(assign_mma_kernel, cudaFuncAttributeMaxDynamicSharedMemorySize, SMEM_SZ);
    cudaFuncSetAttribute(vlad_mma_kernel,  cudaFuncAttributeMaxDynamicSharedMemorySize, SMEM_SZ);

    assign_mma_kernel<<<dim3(8, 32), 256, SMEM_SZ>>>(x, W, b);
    vlad_mma_kernel<<<dim3(4, 32), 256, SMEM_SZ>>>(x, cent);
    norm_kernel<<<32, 256>>>(out);
}

// round 8
// speedup vs baseline: 1.9523x; 1.0773x over previous
#include <cuda_runtime.h>
#include <cuda_bf16.h>
#include <stdint.h>

#define NB   32
#define TT   1024
#define CC_  512
#define KK   64
#define F_EPS 1e-12f

// ---------------------------------------------------------------------------
// Scratch (__device__ globals; allocation-free rule)
// ---------------------------------------------------------------------------
__device__ __nv_bfloat16 g_ahi[(size_t)NB * KK * TT];    // a hi split, [n][k][t]
__device__ __nv_bfloat16 g_alo[(size_t)NB * KK * TT];    // a lo split, [n][k][t]
__device__ __nv_bfloat16 g_whi[(size_t)KK * CC_];        // W hi split
__device__ __nv_bfloat16 g_wlo[(size_t)KK * CC_];        // W lo split
__device__ float         g_asum_part[NB * 8 * KK];       // per t-tile partial sums
__device__ float         g_vlad[(size_t)NB * KK * CC_];  // [n][k][c]
__device__ float         g_scale[NB * KK];               // combined norm scales

// ---------------------------------------------------------------------------
// Helpers (plain sm_80+ PTX only: ldmatrix + mma.sync + cp.async)
// ---------------------------------------------------------------------------
__device__ __forceinline__ uint32_t smem_u32(const void* p) {
    uint32_t a;
    asm("{ .reg .u64 t; cvta.to.shared.u64 t, %1; cvt.u32.u64 %0, t; }"
        : "=r"(a) : "l"(p));
    return a;
}

__device__ __forceinline__ uint32_t swz128(uint32_t off) {  // Swizzle<3,4,3>
    return off ^ ((off >> 3) & 0x70);
}

__device__ __forceinline__ void ldmx4(uint32_t* r, uint32_t addr) {
    asm volatile("ldmatrix.sync.aligned.m8n8.x4.shared.b16 {%0,%1,%2,%3}, [%4];"
                 : "=r"(r[0]), "=r"(r[1]), "=r"(r[2]), "=r"(r[3]) : "r"(addr));
}

__device__ __forceinline__ void mma_bf16(float* d, const uint32_t* a, const uint32_t* b) {
    asm volatile("mma.sync.aligned.m16n8k16.row.col.f32.bf16.bf16.f32 "
                 "{%0,%1,%2,%3}, {%4,%5,%6,%7}, {%8,%9}, {%0,%1,%2,%3};"
                 : "+f"(d[0]), "+f"(d[1]), "+f"(d[2]), "+f"(d[3])
                 : "r"(a[0]), "r"(a[1]), "r"(a[2]), "r"(a[3]), "r"(b[0]), "r"(b[1]));
}

#define CP16(dst, src) \
    asm volatile("cp.async.cg.shared.global [%0], [%1], 16;" :: "r"(dst), "l"(src))
#define CP_COMMIT() asm volatile("cp.async.commit_group;")
#define CP_WAIT0()  asm volatile("cp.async.wait_group 0;")

__device__ __forceinline__ uint32_t pack_bf16x2(float lo, float hi) {
    __nv_bfloat162 v = __floats2bfloat162_rn(lo, hi);
    return reinterpret_cast<uint32_t&>(v);
}

__device__ __forceinline__ void split2(float v, float& h, float& l) {
    __nv_bfloat16 hb = __float2bfloat16(v);
    h = __bfloat162float(hb);
    l = v - h;
}

// smem layout: two 48 KB pipeline stages + aux
#define SS     49152u
#define OAH    0u        // A: 128 rows x 128B (SW128)  16 KB per split
#define OAL    16384u
#define OBH    32768u    // B: 64 rows x 128B            8 KB per split
#define OBL    40960u
#define OAUX   98304u    // 64 floats (bias / asum)
#define OSROW  98560u    // 128 floats (softmax 1/sum)
#define SMEM_SZ 99840u
#define LSTR   66        // fp32 epilogue tile stride

// ---------------------------------------------------------------------------
// Warp-level MMA over one 64-deep chunk at a given stage base.
// A: 128 rows (m) x 64 bf16 (SW128); B: 64 rows (n) x 64 bf16.
// Warp computes acc[2][4][4] covering 32 m x 32 n. Passes: hh, hl, lh.
// ---------------------------------------------------------------------------
__device__ __forceinline__ void warp_mma_chunk(
    float (&acc)[2][4][4], uint32_t sbase, int mBase, int nBase, int lane)
{
    const uint32_t aHi = sbase + OAH, aLo = sbase + OAL;
    const uint32_t bHi = sbase + OBH, bLo = sbase + OBL;
    const int arow  = mBase + (lane & 15);
    const int acol0 = (lane >> 4) * 16;
    const int brow  = nBase + ((lane >> 4) << 3) + (lane & 7);
    const int bcol0 = ((lane >> 3) & 1) * 16;
#pragma unroll
    for (int ks = 0; ks < 4; ks++) {
        uint32_t ah[2][4], al[2][4], bh[2][4], bl[2][4];
#pragma unroll
        for (int mb = 0; mb < 2; mb++) {
            uint32_t off = swz128((uint32_t)((arow + mb * 16) * 128 + ks * 32 + acol0));
            ldmx4(ah[mb], aHi + off);
            ldmx4(al[mb], aLo + off);
        }
#pragma unroll
        for (int np = 0; np < 2; np++) {
            uint32_t off = swz128((uint32_t)((brow + np * 16) * 128 + ks * 32 + bcol0));
            ldmx4(bh[np], bHi + off);
            ldmx4(bl[np], bLo + off);
        }
#pragma unroll
        for (int mb = 0; mb < 2; mb++)
#pragma unroll
            for (int nb = 0; nb < 4; nb++) {
                const uint32_t* ph = &bh[nb >> 1][(nb & 1) * 2];
                const uint32_t* pl = &bl[nb >> 1][(nb & 1) * 2];
                mma_bf16(acc[mb][nb], ah[mb], ph);
                mma_bf16(acc[mb][nb], ah[mb], pl);
                mma_bf16(acc[mb][nb], al[mb], ph);
            }
    }
}

__device__ __forceinline__ void store_frags(
    float* ls, float (&acc)[2][4][4], int mBase, int nBase, int lane)
{
    const int r = lane >> 2, cp = (lane & 3) * 2;
#pragma unroll
    for (int mb = 0; mb < 2; mb++)
#pragma unroll
        for (int nb = 0; nb < 4; nb++) {
            const int row = mBase + mb * 16 + r;
            const int col = nBase + nb * 8 + cp;
            ls[row * LSTR + col]           = acc[mb][nb][0];
            ls[row * LSTR + col + 1]       = acc[mb][nb][1];
            ls[(row + 8) * LSTR + col]     = acc[mb][nb][2];
            ls[(row + 8) * LSTR + col + 1] = acc[mb][nb][3];
        }
}

// ---------------------------------------------------------------------------
// Kernel 0: split W fp32 -> bf16 hi/lo (one-shot, tiny)
// ---------------------------------------------------------------------------
__global__ __launch_bounds__(256) void wsplit_kernel(const float* __restrict__ W)
{
    int i = blockIdx.x * 256 + threadIdx.x;          // grid 32 -> 8192 threads
    float4 v = reinterpret_cast<const float4*>(W)[i];
    float h0,h1,h2,h3,l0,l1,l2,l3;
    split2(v.x,h0,l0); split2(v.y,h1,l1); split2(v.z,h2,l2); split2(v.w,h3,l3);
    uint2 uh = { pack_bf16x2(h0,h1), pack_bf16x2(h2,h3) };
    uint2 ul = { pack_bf16x2(l0,l1), pack_bf16x2(l2,l3) };
    reinterpret_cast<uint2*>(g_whi)[i] = uh;
    reinterpret_cast<uint2*>(g_wlo)[i] = ul;
}

// ---------------------------------------------------------------------------
// Kernel 1 fills
// ---------------------------------------------------------------------------
__device__ __forceinline__ void k1_ldgA(float4 (&v)[8], const float* xb, int c0, int tid) {
#pragma unroll
    for (int r = 0; r < 8; r++) {
        int idx = tid + 256 * r;
        int t = idx >> 4, c4 = (idx & 15) * 4;
        v[r] = *reinterpret_cast<const float4*>(xb + (size_t)t * CC_ + c0 + c4);
    }
}
__device__ __forceinline__ void k1_stsA(char* sm, uint32_t st, const float4 (&v)[8], int tid) {
#pragma unroll
    for (int r = 0; r < 8; r++) {
        int idx = tid + 256 * r;
        int t = idx >> 4, c4 = (idx & 15) * 4;
        float h0,h1,h2,h3,l0,l1,l2,l3;
        split2(v[r].x,h0,l0); split2(v[r].y,h1,l1);
        split2(v[r].z,h2,l2); split2(v[r].w,h3,l3);
        uint2 uh = { pack_bf16x2(h0,h1), pack_bf16x2(h2,h3) };
        uint2 ul = { pack_bf16x2(l0,l1), pack_bf16x2(l2,l3) };
        uint32_t sw = swz128((uint32_t)(t * 128 + c4 * 2));
        *reinterpret_cast<uint2*>(sm + st + OAH + sw) = uh;
        *reinterpret_cast<uint2*>(sm + st + OAL + sw) = ul;
    }
}
__device__ __forceinline__ void k1_cpB(uint32_t sbase, int c0, int tid) {
#pragma unroll
    for (int r = 0; r < 2; r++) {
        int idx = tid + 256 * r;
        int k = idx >> 3, e8 = (idx & 7) * 8;
        uint32_t sw = swz128((uint32_t)(k * 128 + e8 * 2));
        CP16(sbase + OBH + sw, g_whi + (size_t)k * CC_ + c0 + e8);
        CP16(sbase + OBL + sw, g_wlo + (size_t)k * CC_ + c0 + e8);
    }
}

// ---------------------------------------------------------------------------
// Kernel 1: logits GEMM + softmax + bf16 split writeback + asum partials
// grid (8, 32): x = t-tile of 128, y = n. 256 threads (8 warps, 4m x 2n).
// ---------------------------------------------------------------------------
__global__ __launch_bounds__(256, 2)
void assign_mma_kernel(const float* __restrict__ x, const float* __restrict__ b)
{
    extern __shared__ char smem_raw[];
    uint32_t sb0 = smem_u32(smem_raw);
    uint32_t abase = (sb0 + 1023u) & ~1023u;
    char* sm = smem_raw + (abase - sb0);

    const int n   = blockIdx.y;
    const int t0  = blockIdx.x * 128;
    const int tid = threadIdx.x;
    const int wid = tid >> 5, lane = tid & 31;
    const int mBase = (wid & 3) * 32, nBase = (wid >> 2) * 32;

    float* saux = (float*)(sm + OAUX);
    float* srow = (float*)(sm + OSROW);
    if (tid < KK) saux[tid] = b[tid];

    float acc[2][4][4];
#pragma unroll
    for (int mb = 0; mb < 2; mb++)
#pragma unroll
        for (int nb = 0; nb < 4; nb++)
#pragma unroll
            for (int e = 0; e < 4; e++) acc[mb][nb][e] = 0.f;

    const float* xb = x + ((size_t)(n * TT + t0)) * CC_;
    float4 av[8];

    // prologue: chunk0 A+B into stage0, prefetch chunk1 A
    k1_ldgA(av, xb, 0, tid);
    k1_cpB(abase, 0, tid); CP_COMMIT();
    k1_stsA(sm, 0, av, tid);
    k1_ldgA(av, xb, 64, tid);
    CP_WAIT0();
    __syncthreads();

    for (int ci = 0; ci < 8; ci++) {
        const uint32_t cur = (uint32_t)(ci & 1) * SS;
        const uint32_t nxt = (uint32_t)((ci + 1) & 1) * SS;
        if (ci < 7) {
            k1_cpB(abase + nxt, (ci + 1) * 64, tid); CP_COMMIT();
            k1_stsA(sm, nxt, av, tid);
        }
        if (ci < 6) k1_ldgA(av, xb, (ci + 2) * 64, tid);
        warp_mma_chunk(acc, abase + cur, mBase, nBase, lane);
        if (ci < 7) CP_WAIT0();
        __syncthreads();
    }

    // Epilogue: logits -> smem ls[t][k], softmax per row, bf16 split writeback.
    float* ls = (float*)sm;
    store_frags(ls, acc, mBase, nBase, lane);
    __syncthreads();

    if (tid < 128) {
        const int t = tid;
        float mx = -1e30f;
#pragma unroll 8
        for (int k = 0; k < KK; k++) mx = fmaxf(mx, ls[t * LSTR + k] + saux[k]);
        float s = 0.f;
#pragma unroll 8
        for (int k = 0; k < KK; k++) {
            float e = __expf(ls[t * LSTR + k] + saux[k] - mx);
            ls[t * LSTR + k] = e;
            s += e;
        }
        srow[t] = 1.f / s;
    }
    __syncthreads();

#pragma unroll
    for (int i = 0; i < 8; i++) {
        int idx = tid + 256 * i;
        int k = idx >> 5;
        int tq = (idx & 31) * 4;
        float a0 = ls[(tq + 0) * LSTR + k] * srow[tq + 0];
        float a1 = ls[(tq + 1) * LSTR + k] * srow[tq + 1];
        float a2 = ls[(tq + 2) * LSTR + k] * srow[tq + 2];
        float a3 = ls[(tq + 3) * LSTR + k] * srow[tq + 3];
        float h0,h1,h2,h3,l0,l1,l2,l3;
        split2(a0,h0,l0); split2(a1,h1,l1); split2(a2,h2,l2); split2(a3,h3,l3);
        uint2 uh = { pack_bf16x2(h0,h1), pack_bf16x2(h2,h3) };
        uint2 ul = { pack_bf16x2(l0,l1), pack_bf16x2(l2,l3) };
        size_t off = ((size_t)(n * KK + k)) * TT + t0 + tq;
        *reinterpret_cast<uint2*>(g_ahi + off) = uh;
        *reinterpret_cast<uint2*>(g_alo + off) = ul;

        float p = a0 + a1 + a2 + a3;
#pragma unroll
        for (int o = 16; o; o >>= 1) p += __shfl_xor_sync(0xffffffffu, p, o);
        if (lane == 0) g_asum_part[(n * 8 + blockIdx.x) * KK + k] = p;
    }
}

// ---------------------------------------------------------------------------
// Kernel 2 fills
// ---------------------------------------------------------------------------
__device__ __forceinline__ void k2_ldgA(float (&v)[8][4], const float* xb, int tid) {
#pragma unroll
    for (int r = 0; r < 8; r++) {
        int idx = tid + 256 * r;
        int c = idx & 127, tq = (idx >> 7) * 4;
#pragma unroll
        for (int j = 0; j < 4; j++) v[r][j] = xb[(size_t)(tq + j) * CC_ + c];
    }
}
__device__ __forceinline__ void k2_stsA(char* sm, uint32_t st, const float (&v)[8][4], int tid) {
#pragma unroll
    for (int r = 0; r < 8; r++) {
        int idx = tid + 256 * r;
        int c = idx & 127, tq = (idx >> 7) * 4;
        float h0,h1,h2,h3,l0,l1,l2,l3;
        split2(v[r][0],h0,l0); split2(v[r][1],h1,l1);
        split2(v[r][2],h2,l2); split2(v[r][3],h3,l3);
        uint2 uh = { pack_bf16x2(h0,h1), pack_bf16x2(h2,h3) };
        uint2 ul = { pack_bf16x2(l0,l1), pack_bf16x2(l2,l3) };
        uint32_t sw = swz128((uint32_t)(c * 128 + tq * 2));
        *reinterpret_cast<uint2*>(sm + st + OAH + sw) = uh;
        *reinterpret_cast<uint2*>(sm + st + OAL + sw) = ul;
    }
}
__device__ __forceinline__ void k2_cpB(uint32_t sbase, int n, int tch, int tid) {
#pragma unroll
    for (int r = 0; r < 2; r++) {
        int idx = tid + 256 * r;
        int k = idx >> 3, e8 = (idx & 7) * 8;
        uint32_t sw = swz128((uint32_t)(k * 128 + e8 * 2));
        size_t goff = ((size_t)(n * KK + k)) * TT + tch + e8;
        CP16(sbase + OBH + sw, g_ahi + goff);
        CP16(sbase + OBL + sw, g_alo + goff);
    }
}

// ---------------------------------------------------------------------------
// Kernel 2: vlad GEMM. grid (4, 32): x = c-tile of 128, y = n. 256 threads.
// ---------------------------------------------------------------------------
__global__ __launch_bounds__(256, 2)
void vlad_mma_kernel(const float* __restrict__ x, const float* __restrict__ cent)
{
    extern __shared__ char smem_raw[];
    uint32_t sb0 = smem_u32(smem_raw);
    uint32_t abase = (sb0 + 1023u) & ~1023u;
    char* sm = smem_raw + (abase - sb0);

    const int n   = blockIdx.y;
    const int c0  = blockIdx.x * 128;
    const int tid = threadIdx.x;
    const int wid = tid >> 5, lane = tid & 31;
    const int mBase = (wid & 3) * 32, nBase = (wid >> 2) * 32;

    float* saux = (float*)(sm + OAUX);
    if (tid < KK) {
        float s = 0.f;
#pragma unroll
        for (int p = 0; p < 8; p++) s += g_asum_part[(n * 8 + p) * KK + tid];
        saux[tid] = s;
    }

    float acc[2][4][4];
#pragma unroll
    for (int mb = 0; mb < 2; mb++)
#pragma unroll
        for (int nb = 0; nb < 4; nb++)
#pragma unroll
            for (int e = 0; e < 4; e++) acc[mb][nb][e] = 0.f;

    const float* xn = x + (size_t)n * TT * CC_ + c0;
    float av[8][4];

    // prologue
    k2_ldgA(av, xn, tid);
    k2_cpB(abase, n, 0, tid); CP_COMMIT();
    k2_stsA(sm, 0, av, tid);
    k2_ldgA(av, xn + (size_t)64 * CC_, tid);
    CP_WAIT0();
    __syncthreads();

    for (int ti = 0; ti < 16; ti++) {
        const uint32_t cur = (uint32_t)(ti & 1) * SS;
        const uint32_t nxt = (uint32_t)((ti + 1) & 1) * SS;
        if (ti < 15) {
            k2_cpB(abase + nxt, n, (ti + 1) * 64, tid); CP_COMMIT();
            k2_stsA(sm, nxt, av, tid);
        }
        if (ti < 14) k2_ldgA(av, xn + (size_t)((ti + 2) * 64) * CC_, tid);
        warp_mma_chunk(acc, abase + cur, mBase, nBase, lane);
        if (ti < 15) CP_WAIT0();
        __syncthreads();
    }

    // Epilogue: D[c][k] -> smem, then transposed coalesced writeback
    float* vs = (float*)sm;
    store_frags(vs, acc, mBase, nBase, lane);
    __syncthreads();

#pragma unroll
    for (int i = 0; i < 8; i++) {
        int idx = tid + 256 * i;
        int k = idx >> 5;
        int cq = (idx & 31) * 4;
        const float as = saux[k];
        float4 cv = *reinterpret_cast<const float4*>(cent + (size_t)k * CC_ + c0 + cq);
        float4 o;
        o.x = vs[(cq + 0) * LSTR + k] - as * cv.x;
        o.y = vs[(cq + 1) * LSTR + k] - as * cv.y;
        o.z = vs[(cq + 2) * LSTR + k] - as * cv.z;
        o.w = vs[(cq + 3) * LSTR + k] - as * cv.w;
        *reinterpret_cast<float4*>(g_vlad + ((size_t)(n * KK + k)) * CC_ + c0 + cq) = o;
    }
}

// ---------------------------------------------------------------------------
// Kernel 3a: compute combined scales. grid 32.
// ---------------------------------------------------------------------------
__global__ __launch_bounds__(256) void norm_reduce_kernel()
{
    const int n = blockIdx.x;
    const int tid = threadIdx.x;
    const int warp = tid >> 5, lane = tid & 31;
    __shared__ float sscale[KK];
    __shared__ float sred[8];

    const float* v = g_vlad + (size_t)n * KK * CC_;

    for (int k = warp; k < KK; k += 8) {
        float ss = 0.f;
        const float* row = v + (size_t)k * CC_;
        for (int c = lane * 4; c < CC_; c += 128) {
            float4 q = *reinterpret_cast<const float4*>(row + c);
            ss += q.x * q.x + q.y * q.y + q.z * q.z + q.w * q.w;
        }
#pragma unroll
        for (int off = 16; off; off >>= 1) ss += __shfl_xor_sync(0xffffffffu, ss, off);
        if (lane == 0) sscale[k] = ss;
    }
    __syncthreads();

    float gpart = 0.f;
    if (tid < KK) {
        float ss = sscale[tid];
        float sc = 1.f / fmaxf(sqrtf(ss), F_EPS);
        gpart = ss * sc * sc;
        sscale[tid] = sc;
    }
#pragma unroll
    for (int off = 16; off; off >>= 1) gpart += __shfl_xor_sync(0xffffffffu, gpart, off);
    if (lane == 0) sred[warp] = gpart;
    __syncthreads();
    if (tid == 0) sred[0] = 1.f / fmaxf(sqrtf(sred[0] + sred[1]), F_EPS);
    __syncthreads();

    if (tid < KK) g_scale[n * KK + tid] = sscale[tid] * sred[0];
}

// ---------------------------------------------------------------------------
// Kernel 3b: apply scales. grid (8, 32): 4096 elems per CTA.
// ---------------------------------------------------------------------------
__global__ __launch_bounds__(256) void norm_apply_kernel(float* __restrict__ out)
{
    const int n = blockIdx.y;
    const int base = blockIdx.x * 4096;
    const int tid = threadIdx.x;
    __shared__ float ss[KK];
    if (tid < KK) ss[tid] = g_scale[n * KK + tid];
    __syncthreads();

    const float* v = g_vlad + (size_t)n * KK * CC_;
    float* o = out + (size_t)n * KK * CC_;
#pragma unroll
    for (int i = 0; i < 4; i++) {
        int idx = base + tid * 4 + i * 1024;
        const float s = ss[idx >> 9];
        float4 q = *reinterpret_cast<const float4*>(v + idx);
        q.x *= s; q.y *= s; q.z *= s; q.w *= s;
        *reinterpret_cast<float4*>(o + idx) = q;
    }
}

// ---------------------------------------------------------------------------
extern "C" void kernel_launch(void* const* d_in, const int* in_sizes, int n_in,
                              void* d_out, int out_size)
{
    const float* x    = (const float*)d_in[0];   // [32,1024,512]
    const float* W    = (const float*)d_in[1];   // [64,512]
    const float* b    = (const float*)d_in[2];   // [64]
    const float* cent = (const float*)d_in[3];   // [64,512]
    float* out = (float*)d_out;                  // [32, 32768]

    cudaFuncSetAttribute(assign_mma_kernel, cudaFuncAttributeMaxDynamicSharedMemorySize, SMEM_SZ);
    cudaFuncSetAttribute(vlad_mma_kernel,  cudaFuncAttributeMaxDynamicSharedMemorySize, SMEM_SZ);

    wsplit_kernel<<<32, 256>>>(W);
    assign_mma_kernel<<<dim3(8, 32), 256, SMEM_SZ>>>(x, b);
    vlad_mma_kernel<<<dim3(4, 32), 256, SMEM_SZ>>>(x, cent);
    norm_reduce_kernel<<<32, 256>>>();
    norm_apply_kernel<<<dim3(8, 32), 256>>>(out);
}

// round 11
// speedup vs baseline: 2.1818x; 1.1176x over previous
#include <cuda_runtime.h>
#include <cuda_bf16.h>
#include <stdint.h>

#define NB   32
#define TT   1024
#define CC_  512
#define KK   64
#define F_EPS 1e-12f

// ---------------------------------------------------------------------------
// Scratch (__device__ globals; allocation-free rule)
// ---------------------------------------------------------------------------
__device__ __nv_bfloat16 g_ahi[(size_t)NB * KK * TT];    // a hi split, [n][k][t]
__device__ __nv_bfloat16 g_alo[(size_t)NB * KK * TT];    // a lo split, [n][k][t]
__device__ __nv_bfloat16 g_whi[(size_t)KK * CC_];        // W hi split
__device__ __nv_bfloat16 g_wlo[(size_t)KK * CC_];        // W lo split
__device__ float         g_asum_part[NB * 8 * KK];       // per t-tile partial sums
__device__ float         g_vlad[(size_t)NB * KK * CC_];  // [n][k][c]
__device__ float         g_ss_part[NB * 4 * KK];         // per c-tile sumsq partials
__device__ float         g_scale[NB * KK];               // combined norm scales

// ---------------------------------------------------------------------------
// Helpers (plain sm_80+ PTX only: ldmatrix + mma.sync + cp.async)
// ---------------------------------------------------------------------------
__device__ __forceinline__ uint32_t smem_u32(const void* p) {
    uint32_t a;
    asm("{ .reg .u64 t; cvta.to.shared.u64 t, %1; cvt.u32.u64 %0, t; }"
        : "=r"(a) : "l"(p));
    return a;
}

__device__ __forceinline__ uint32_t swz128(uint32_t off) {  // Swizzle<3,4,3>
    return off ^ ((off >> 3) & 0x70);
}

__device__ __forceinline__ void ldmx4(uint32_t* r, uint32_t addr) {
    asm volatile("ldmatrix.sync.aligned.m8n8.x4.shared.b16 {%0,%1,%2,%3}, [%4];"
                 : "=r"(r[0]), "=r"(r[1]), "=r"(r[2]), "=r"(r[3]) : "r"(addr));
}

__device__ __forceinline__ void mma_bf16(float* d, const uint32_t* a, const uint32_t* b) {
    asm volatile("mma.sync.aligned.m16n8k16.row.col.f32.bf16.bf16.f32 "
                 "{%0,%1,%2,%3}, {%4,%5,%6,%7}, {%8,%9}, {%0,%1,%2,%3};"
                 : "+f"(d[0]), "+f"(d[1]), "+f"(d[2]), "+f"(d[3])
                 : "r"(a[0]), "r"(a[1]), "r"(a[2]), "r"(a[3]), "r"(b[0]), "r"(b[1]));
}

#define CP16(dst, src) \
    asm volatile("cp.async.cg.shared.global [%0], [%1], 16;" :: "r"(dst), "l"(src))
#define CP_COMMIT() asm volatile("cp.async.commit_group;")
#define CP_WAIT0()  asm volatile("cp.async.wait_group 0;")

__device__ __forceinline__ uint32_t pack_bf16x2(float lo, float hi) {
    __nv_bfloat162 v = __floats2bfloat162_rn(lo, hi);
    return reinterpret_cast<uint32_t&>(v);
}

__device__ __forceinline__ void split2(float v, float& h, float& l) {
    __nv_bfloat16 hb = __float2bfloat16(v);
    h = __bfloat162float(hb);
    l = v - h;
}

// smem layout: two 48 KB pipeline stages + aux
#define SS     49152u
#define OAH    0u        // A: 128 rows x 128B (SW128)  16 KB per split
#define OAL    16384u
#define OBH    32768u    // B: 64 rows x 128B            8 KB per split
#define OBL    40960u
#define OAUX   98304u    // 64 floats (bias / asum)
#define OSROW  98560u    // 128 floats (softmax 1/sum)
#define SMEM_SZ 99840u
#define LSTR   66        // fp32 epilogue tile stride

// ---------------------------------------------------------------------------
// Warp-level MMA over one 64-deep chunk at a given stage base.
// ---------------------------------------------------------------------------
__device__ __forceinline__ void warp_mma_chunk(
    float (&acc)[2][4][4], uint32_t sbase, int mBase, int nBase, int lane)
{
    const uint32_t aHi = sbase + OAH, aLo = sbase + OAL;
    const uint32_t bHi = sbase + OBH, bLo = sbase + OBL;
    const int arow  = mBase + (lane & 15);
    const int acol0 = (lane >> 4) * 16;
    const int brow  = nBase + ((lane >> 4) << 3) + (lane & 7);
    const int bcol0 = ((lane >> 3) & 1) * 16;
#pragma unroll
    for (int ks = 0; ks < 4; ks++) {
        uint32_t ah[2][4], al[2][4], bh[2][4], bl[2][4];
#pragma unroll
        for (int mb = 0; mb < 2; mb++) {
            uint32_t off = swz128((uint32_t)((arow + mb * 16) * 128 + ks * 32 + acol0));
            ldmx4(ah[mb], aHi + off);
            ldmx4(al[mb], aLo + off);
        }
#pragma unroll
        for (int np = 0; np < 2; np++) {
            uint32_t off = swz128((uint32_t)((brow + np * 16) * 128 + ks * 32 + bcol0));
            ldmx4(bh[np], bHi + off);
            ldmx4(bl[np], bLo + off);
        }
#pragma unroll
        for (int mb = 0; mb < 2; mb++)
#pragma unroll
            for (int nb = 0; nb < 4; nb++) {
                const uint32_t* ph = &bh[nb >> 1][(nb & 1) * 2];
                const uint32_t* pl = &bl[nb >> 1][(nb & 1) * 2];
                mma_bf16(acc[mb][nb], ah[mb], ph);
                mma_bf16(acc[mb][nb], ah[mb], pl);
                mma_bf16(acc[mb][nb], al[mb], ph);
            }
    }
}

__device__ __forceinline__ void store_frags(
    float* ls, float (&acc)[2][4][4], int mBase, int nBase, int lane)
{
    const int r = lane >> 2, cp = (lane & 3) * 2;
#pragma unroll
    for (int mb = 0; mb < 2; mb++)
#pragma unroll
        for (int nb = 0; nb < 4; nb++) {
            const int row = mBase + mb * 16 + r;
            const int col = nBase + nb * 8 + cp;
            ls[row * LSTR + col]           = acc[mb][nb][0];
            ls[row * LSTR + col + 1]       = acc[mb][nb][1];
            ls[(row + 8) * LSTR + col]     = acc[mb][nb][2];
            ls[(row + 8) * LSTR + col + 1] = acc[mb][nb][3];
        }
}

// ---------------------------------------------------------------------------
// Kernel 0: split W fp32 -> bf16 hi/lo (one-shot, tiny)
// ---------------------------------------------------------------------------
__global__ __launch_bounds__(256) void wsplit_kernel(const float* __restrict__ W)
{
    int i = blockIdx.x * 256 + threadIdx.x;
    float4 v = reinterpret_cast<const float4*>(W)[i];
    float h0,h1,h2,h3,l0,l1,l2,l3;
    split2(v.x,h0,l0); split2(v.y,h1,l1); split2(v.z,h2,l2); split2(v.w,h3,l3);
    uint2 uh = { pack_bf16x2(h0,h1), pack_bf16x2(h2,h3) };
    uint2 ul = { pack_bf16x2(l0,l1), pack_bf16x2(l2,l3) };
    reinterpret_cast<uint2*>(g_whi)[i] = uh;
    reinterpret_cast<uint2*>(g_wlo)[i] = ul;
}

// ---------------------------------------------------------------------------
// Kernel 1 fills
// ---------------------------------------------------------------------------
__device__ __forceinline__ void k1_ldgA(float4 (&v)[8], const float* xb, int c0, int tid) {
#pragma unroll
    for (int r = 0; r < 8; r++) {
        int idx = tid + 256 * r;
        int t = idx >> 4, c4 = (idx & 15) * 4;
        v[r] = *reinterpret_cast<const float4*>(xb + (size_t)t * CC_ + c0 + c4);
    }
}
__device__ __forceinline__ void k1_stsA(char* sm, uint32_t st, const float4 (&v)[8], int tid) {
#pragma unroll
    for (int r = 0; r < 8; r++) {
        int idx = tid + 256 * r;
        int t = idx >> 4, c4 = (idx & 15) * 4;
        float h0,h1,h2,h3,l0,l1,l2,l3;
        split2(v[r].x,h0,l0); split2(v[r].y,h1,l1);
        split2(v[r].z,h2,l2); split2(v[r].w,h3,l3);
        uint2 uh = { pack_bf16x2(h0,h1), pack_bf16x2(h2,h3) };
        uint2 ul = { pack_bf16x2(l0,l1), pack_bf16x2(l2,l3) };
        uint32_t sw = swz128((uint32_t)(t * 128 + c4 * 2));
        *reinterpret_cast<uint2*>(sm + st + OAH + sw) = uh;
        *reinterpret_cast<uint2*>(sm + st + OAL + sw) = ul;
    }
}
__device__ __forceinline__ void k1_cpB(uint32_t sbase, int c0, int tid) {
#pragma unroll
    for (int r = 0; r < 2; r++) {
        int idx = tid + 256 * r;
        int k = idx >> 3, e8 = (idx & 7) * 8;
        uint32_t sw = swz128((uint32_t)(k * 128 + e8 * 2));
        CP16(sbase + OBH + sw, g_whi + (size_t)k * CC_ + c0 + e8);
        CP16(sbase + OBL + sw, g_wlo + (size_t)k * CC_ + c0 + e8);
    }
}

// ---------------------------------------------------------------------------
// Kernel 1: logits GEMM + softmax + bf16 split writeback + asum partials
// grid (8, 32): x = t-tile of 128, y = n. 256 threads (8 warps, 4m x 2n).
// ---------------------------------------------------------------------------
__global__ __launch_bounds__(256, 2)
void assign_mma_kernel(const float* __restrict__ x, const float* __restrict__ b)
{
    extern __shared__ char smem_raw[];
    uint32_t sb0 = smem_u32(smem_raw);
    uint32_t abase = (sb0 + 1023u) & ~1023u;
    char* sm = smem_raw + (abase - sb0);

    const int n   = blockIdx.y;
    const int t0  = blockIdx.x * 128;
    const int tid = threadIdx.x;
    const int wid = tid >> 5, lane = tid & 31;
    const int mBase = (wid & 3) * 32, nBase = (wid >> 2) * 32;

    float* saux = (float*)(sm + OAUX);
    float* srow = (float*)(sm + OSROW);
    if (tid < KK) saux[tid] = b[tid];

    float acc[2][4][4];
#pragma unroll
    for (int mb = 0; mb < 2; mb++)
#pragma unroll
        for (int nb = 0; nb < 4; nb++)
#pragma unroll
            for (int e = 0; e < 4; e++) acc[mb][nb][e] = 0.f;

    const float* xb = x + ((size_t)(n * TT + t0)) * CC_;
    float4 av[8];

    k1_ldgA(av, xb, 0, tid);
    k1_cpB(abase, 0, tid); CP_COMMIT();
    k1_stsA(sm, 0, av, tid);
    k1_ldgA(av, xb, 64, tid);
    CP_WAIT0();
    __syncthreads();

    for (int ci = 0; ci < 8; ci++) {
        const uint32_t cur = (uint32_t)(ci & 1) * SS;
        const uint32_t nxt = (uint32_t)((ci + 1) & 1) * SS;
        if (ci < 7) {
            k1_cpB(abase + nxt, (ci + 1) * 64, tid); CP_COMMIT();
            k1_stsA(sm, nxt, av, tid);
        }
        if (ci < 6) k1_ldgA(av, xb, (ci + 2) * 64, tid);
        warp_mma_chunk(acc, abase + cur, mBase, nBase, lane);
        if (ci < 7) CP_WAIT0();
        __syncthreads();
    }

    float* ls = (float*)sm;
    store_frags(ls, acc, mBase, nBase, lane);
    __syncthreads();

    if (tid < 128) {
        const int t = tid;
        float mx = -1e30f;
#pragma unroll 8
        for (int k = 0; k < KK; k++) mx = fmaxf(mx, ls[t * LSTR + k] + saux[k]);
        float s = 0.f;
#pragma unroll 8
        for (int k = 0; k < KK; k++) {
            float e = __expf(ls[t * LSTR + k] + saux[k] - mx);
            ls[t * LSTR + k] = e;
            s += e;
        }
        srow[t] = 1.f / s;
    }
    __syncthreads();

#pragma unroll
    for (int i = 0; i < 8; i++) {
        int idx = tid + 256 * i;
        int k = idx >> 5;
        int tq = (idx & 31) * 4;
        float a0 = ls[(tq + 0) * LSTR + k] * srow[tq + 0];
        float a1 = ls[(tq + 1) * LSTR + k] * srow[tq + 1];
        float a2 = ls[(tq + 2) * LSTR + k] * srow[tq + 2];
        float a3 = ls[(tq + 3) * LSTR + k] * srow[tq + 3];
        float h0,h1,h2,h3,l0,l1,l2,l3;
        split2(a0,h0,l0); split2(a1,h1,l1); split2(a2,h2,l2); split2(a3,h3,l3);
        uint2 uh = { pack_bf16x2(h0,h1), pack_bf16x2(h2,h3) };
        uint2 ul = { pack_bf16x2(l0,l1), pack_bf16x2(l2,l3) };
        size_t off = ((size_t)(n * KK + k)) * TT + t0 + tq;
        *reinterpret_cast<uint2*>(g_ahi + off) = uh;
        *reinterpret_cast<uint2*>(g_alo + off) = ul;

        float p = a0 + a1 + a2 + a3;
#pragma unroll
        for (int o = 16; o; o >>= 1) p += __shfl_xor_sync(0xffffffffu, p, o);
        if (lane == 0) g_asum_part[(n * 8 + blockIdx.x) * KK + k] = p;
    }
}

// ---------------------------------------------------------------------------
// Kernel 2 fills
// ---------------------------------------------------------------------------
__device__ __forceinline__ void k2_ldgA(float (&v)[8][4], const float* xb, int tid) {
#pragma unroll
    for (int r = 0; r < 8; r++) {
        int idx = tid + 256 * r;
        int c = idx & 127, tq = (idx >> 7) * 4;
#pragma unroll
        for (int j = 0; j < 4; j++) v[r][j] = xb[(size_t)(tq + j) * CC_ + c];
    }
}
__device__ __forceinline__ void k2_stsA(char* sm, uint32_t st, const float (&v)[8][4], int tid) {
#pragma unroll
    for (int r = 0; r < 8; r++) {
        int idx = tid + 256 * r;
        int c = idx & 127, tq = (idx >> 7) * 4;
        float h0,h1,h2,h3,l0,l1,l2,l3;
        split2(v[r][0],h0,l0); split2(v[r][1],h1,l1);
        split2(v[r][2],h2,l2); split2(v[r][3],h3,l3);
        uint2 uh = { pack_bf16x2(h0,h1), pack_bf16x2(h2,h3) };
        uint2 ul = { pack_bf16x2(l0,l1), pack_bf16x2(l2,l3) };
        uint32_t sw = swz128((uint32_t)(c * 128 + tq * 2));
        *reinterpret_cast<uint2*>(sm + st + OAH + sw) = uh;
        *reinterpret_cast<uint2*>(sm + st + OAL + sw) = ul;
    }
}
__device__ __forceinline__ void k2_cpB(uint32_t sbase, int n, int tch, int tid) {
#pragma unroll
    for (int r = 0; r < 2; r++) {
        int idx = tid + 256 * r;
        int k = idx >> 3, e8 = (idx & 7) * 8;
        uint32_t sw = swz128((uint32_t)(k * 128 + e8 * 2));
        size_t goff = ((size_t)(n * KK + k)) * TT + tch + e8;
        CP16(sbase + OBH + sw, g_ahi + goff);
        CP16(sbase + OBL + sw, g_alo + goff);
    }
}

// ---------------------------------------------------------------------------
// Kernel 2: vlad GEMM + fused sumsq partials. grid (4, 32). 256 threads.
// ---------------------------------------------------------------------------
__global__ __launch_bounds__(256, 2)
void vlad_mma_kernel(const float* __restrict__ x, const float* __restrict__ cent)
{
    extern __shared__ char smem_raw[];
    uint32_t sb0 = smem_u32(smem_raw);
    uint32_t abase = (sb0 + 1023u) & ~1023u;
    char* sm = smem_raw + (abase - sb0);

    const int n   = blockIdx.y;
    const int c0  = blockIdx.x * 128;
    const int tid = threadIdx.x;
    const int wid = tid >> 5, lane = tid & 31;
    const int mBase = (wid & 3) * 32, nBase = (wid >> 2) * 32;

    float* saux = (float*)(sm + OAUX);
    if (tid < KK) {
        float s = 0.f;
#pragma unroll
        for (int p = 0; p < 8; p++) s += g_asum_part[(n * 8 + p) * KK + tid];
        saux[tid] = s;
    }

    float acc[2][4][4];
#pragma unroll
    for (int mb = 0; mb < 2; mb++)
#pragma unroll
        for (int nb = 0; nb < 4; nb++)
#pragma unroll
            for (int e = 0; e < 4; e++) acc[mb][nb][e] = 0.f;

    const float* xn = x + (size_t)n * TT * CC_ + c0;
    float av[8][4];

    k2_ldgA(av, xn, tid);
    k2_cpB(abase, n, 0, tid); CP_COMMIT();
    k2_stsA(sm, 0, av, tid);
    k2_ldgA(av, xn + (size_t)64 * CC_, tid);
    CP_WAIT0();
    __syncthreads();

    for (int ti = 0; ti < 16; ti++) {
        const uint32_t cur = (uint32_t)(ti & 1) * SS;
        const uint32_t nxt = (uint32_t)((ti + 1) & 1) * SS;
        if (ti < 15) {
            k2_cpB(abase + nxt, n, (ti + 1) * 64, tid); CP_COMMIT();
            k2_stsA(sm, nxt, av, tid);
        }
        if (ti < 14) k2_ldgA(av, xn + (size_t)((ti + 2) * 64) * CC_, tid);
        warp_mma_chunk(acc, abase + cur, mBase, nBase, lane);
        if (ti < 15) CP_WAIT0();
        __syncthreads();
    }

    // Epilogue: writeback + fused per-(n,k,c-tile) sum-of-squares partials.
    float* vs = (float*)sm;
    store_frags(vs, acc, mBase, nBase, lane);
    __syncthreads();

#pragma unroll
    for (int i = 0; i < 8; i++) {
        int idx = tid + 256 * i;
        int k = idx >> 5;                 // = wid + 8*i, uniform per warp
        int cq = (idx & 31) * 4;
        const float as = saux[k];
        float4 cv = *reinterpret_cast<const float4*>(cent + (size_t)k * CC_ + c0 + cq);
        float4 o;
        o.x = vs[(cq + 0) * LSTR + k] - as * cv.x;
        o.y = vs[(cq + 1) * LSTR + k] - as * cv.y;
        o.z = vs[(cq + 2) * LSTR + k] - as * cv.z;
        o.w = vs[(cq + 3) * LSTR + k] - as * cv.w;
        *reinterpret_cast<float4*>(g_vlad + ((size_t)(n * KK + k)) * CC_ + c0 + cq) = o;

        float ssq = o.x * o.x + o.y * o.y + o.z * o.z + o.w * o.w;
#pragma unroll
        for (int off = 16; off; off >>= 1) ssq += __shfl_xor_sync(0xffffffffu, ssq, off);
        if (lane == 0) g_ss_part[(n * 4 + blockIdx.x) * KK + k] = ssq;
    }
}

// ---------------------------------------------------------------------------
// Kernel 3a: combine sumsq partials -> scales. grid 32, 64 threads. ~1us.
// ---------------------------------------------------------------------------
__global__ __launch_bounds__(64) void norm_scale_kernel()
{
    const int n = blockIdx.x;
    const int k = threadIdx.x;
    const int wid = k >> 5, lane = k & 31;
    __shared__ float sred[2];

    float ss = 0.f;
#pragma unroll
    for (int p = 0; p < 4; p++) ss += g_ss_part[(n * 4 + p) * KK + k];
    const float sc = 1.f / fmaxf(sqrtf(ss), F_EPS);
    float gp = ss * sc * sc;
#pragma unroll
    for (int off = 16; off; off >>= 1) gp += __shfl_xor_sync(0xffffffffu, gp, off);
    if (lane == 0) sred[wid] = gp;
    __syncthreads();
    const float gscale = 1.f / fmaxf(sqrtf(sred[0] + sred[1]), F_EPS);
    g_scale[n * KK + k] = sc * gscale;
}

// ---------------------------------------------------------------------------
// Kernel 3b: apply scales. grid (8, 32): 4096 elems per CTA.
// ---------------------------------------------------------------------------
__global__ __launch_bounds__(256) void norm_apply_kernel(float* __restrict__ out)
{
    const int n = blockIdx.y;
    const int base = blockIdx.x * 4096;
    const int tid = threadIdx.x;
    __shared__ float ss[KK];
    if (tid < KK) ss[tid] = g_scale[n * KK + tid];
    __syncthreads();

    const float* v = g_vlad + (size_t)n * KK * CC_;
    float* o = out + (size_t)n * KK * CC_;
#pragma unroll
    for (int i = 0; i < 4; i++) {
        int idx = base + tid * 4 + i * 1024;
        const float s = ss[idx >> 9];
        float4 q = *reinterpret_cast<const float4*>(v + idx);
        q.x *= s; q.y *= s; q.z *= s; q.w *= s;
        *reinterpret_cast<float4*>(o + idx) = q;
    }
}

// ---------------------------------------------------------------------------
extern "C" void kernel_launch(void* const* d_in, const int* in_sizes, int n_in,
                              void* d_out, int out_size)
{
    const float* x    = (const float*)d_in[0];   // [32,1024,512]
    const float* W    = (const float*)d_in[1];   // [64,512]
    const float* b    = (const float*)d_in[2];   // [64]
    const float* cent = (const float*)d_in[3];   // [64,512]
    float* out = (float*)d_out;                  // [32, 32768]

    cudaFuncSetAttribute(assign_mma_kernel, cudaFuncAttributeMaxDynamicSharedMemorySize, SMEM_SZ);
    cudaFuncSetAttribute(vlad_mma_kernel,  cudaFuncAttributeMaxDynamicSharedMemorySize, SMEM_SZ);

    wsplit_kernel<<<32, 256>>>(W);
    assign_mma_kernel<<<dim3(8, 32), 256, SMEM_SZ>>>(x, b);
    vlad_mma_kernel<<<dim3(4, 32), 256, SMEM_SZ>>>(x, cent);
    norm_scale_kernel<<<32, 64>>>();
    norm_apply_kernel<<<dim3(8, 32), 256>>>(out);
}